// round 10
// baseline (speedup 1.0000x reference)
#include <cuda_runtime.h>
#include <cuda_fp16.h>
#include <math.h>
#include <stdint.h>

#define BB 128
#define SS 512
#define NN 32
#define DD 512
#define HH 2
#define MM (BB*NN)   // 4096 rows

#define KCH 64                  // fp16 elements per pipeline chunk (128 B/row)
#define HPITCH 72               // smem row pitch in halves (144 B, conflict-free ldsm)
#define ABYTES (128*HPITCH*2)   // 18432: 128-row operand per stage
#define STGB (2*ABYTES)         // 36864 per stage (A128 + B128)
#define NSTG 3
#define SMEM_DYN (NSTG*STGB)    // 110592 -> 2 CTAs/SM

#define ABYTES2 (64*HPITCH*2)   // 9216: 64-row A tile
#define STGB2 (ABYTES2 + ABYTES) // 27648 per stage (A64 + B128)
#define SMEM_DYN2 (NSTG*STGB2)  // 82944 -> 2 CTAs/SM

// ---------------- scratch (device globals; no allocation) ----------------
__device__ int   invmap_buf[BB*SS];
__device__ int   perm_buf[BB*NN];
__device__ int   V_buf[BB];
__device__ float  buf_nodeF[MM*DD];       // fp32 final node (for assembly)
__device__ float  buf_popart[8*BB*DD];    // assemble partial max
__device__ __half buf_numencH[MM*DD];
__device__ __half buf_t3h[MM*DD];
__device__ __half buf_t4h[MM*DD];
__device__ __half buf_ni1h[MM*DD];
__device__ __half buf_ni2h[MM*DD];
__device__ __half buf_ninfoh[MM*DD];
__device__ __half buf_nodeH[2][MM*DD];
__device__ __half buf_WT[16*DD*DD];       // transposed fp16 weights [N,K]

// ---------------- helpers ----------------
__device__ __forceinline__ uint32_t smem_u32(const void* p) {
    return (uint32_t)__cvta_generic_to_shared(p);
}
__device__ __forceinline__ void cp_async16(uint32_t dst, const void* src) {
    asm volatile("cp.async.cg.shared.global [%0], [%1], 16;" :: "r"(dst), "l"(src));
}
__device__ __forceinline__ void mma_f16(float* c, const uint32_t* a,
                                        uint32_t b0, uint32_t b1) {
    asm volatile("mma.sync.aligned.m16n8k16.row.col.f32.f16.f16.f32 "
                 "{%0,%1,%2,%3}, {%4,%5,%6,%7}, {%8,%9}, {%0,%1,%2,%3};"
                 : "+f"(c[0]), "+f"(c[1]), "+f"(c[2]), "+f"(c[3])
                 : "r"(a[0]), "r"(a[1]), "r"(a[2]), "r"(a[3]), "r"(b0), "r"(b1));
}
__device__ __forceinline__ void ldsm_x4(uint32_t addr, uint32_t* r) {
    asm volatile("ldmatrix.sync.aligned.m8n8.x4.shared.b16 {%0,%1,%2,%3}, [%4];"
                 : "=r"(r[0]), "=r"(r[1]), "=r"(r[2]), "=r"(r[3]) : "r"(addr));
}

// ---------------- meta: invmap + rank permutation + valid count ----------------
__global__ void build_meta(const int* __restrict__ order, const int* __restrict__ pos,
                           int* __restrict__ invmap, int* __restrict__ perm,
                           int* __restrict__ Vv) {
    int b = blockIdx.x, tid = threadIdx.x;    // 512 threads
    __shared__ int ord[NN];
    if (tid < NN) ord[tid] = order[b*NN + tid];
    invmap[b*SS + tid] = -1;
    __syncthreads();
    if (tid < NN) {
        int p = pos[b*NN + tid];
        if (p >= 0) invmap[b*SS + p] = b*NN + tid;
        int o = ord[tid];
        bool valid = o > 0;
        int cntLess = 0, cntValid = 0, cntPadB = 0;
        #pragma unroll
        for (int m = 0; m < NN; m++) {
            int om = ord[m];
            bool vm = om > 0;
            cntValid += vm ? 1 : 0;
            cntLess  += (vm && om < o) ? 1 : 0;
            cntPadB  += (!vm && m < tid) ? 1 : 0;
        }
        int r = valid ? cntLess : (cntValid + cntPadB);
        perm[b*NN + r] = tid;
        if (tid == 0) Vv[b] = cntValid;
    }
}

// ---------------- fp32 -> fp16 convert ----------------
__global__ void f2h(const float2* __restrict__ src, __half2* __restrict__ dst, int n2) {
    int i = blockIdx.x*blockDim.x + threadIdx.x;
    int stride = gridDim.x*blockDim.x;
    for (; i < n2; i += stride) dst[i] = __float22half2_rn(src[i]);
}

// ---------------- single-launch weight transpose ([K,N]->[N,K] fp16) -----------
struct TJob { const float* src; __half* d1; __half* d2; int gate; };
struct TArgs { TJob j[14]; };

__global__ void transpose_all(TArgs A) {
    TJob job = A.j[blockIdx.z];
    __shared__ float t1s[32][33], t2s[32][33];
    int k0 = blockIdx.x*32, n0 = blockIdx.y*32;
    int tx = threadIdx.x, ty = threadIdx.y;
    if (!job.gate) {
        #pragma unroll
        for (int i = 0; i < 4; i++)
            t1s[ty + i*8][tx] = job.src[(size_t)(k0 + ty + i*8)*DD + n0 + tx];
        __syncthreads();
        #pragma unroll
        for (int i = 0; i < 4; i++)
            job.d1[(size_t)(n0 + ty + i*8)*DD + k0 + tx] = __float2half(t1s[tx][ty + i*8]);
    } else {
        #pragma unroll
        for (int i = 0; i < 4; i++) {
            int k = k0 + ty + i*8, n = n0 + tx;
            float w0 = job.src[(size_t)k*DD + n];
            float w1 = job.src[(size_t)(DD + k)*DD + n];
            float w2 = job.src[(size_t)(2*DD + k)*DD + n];
            float w3 = job.src[(size_t)(3*DD + k)*DD + n];
            t1s[ty + i*8][tx] = w0 + w2 + w3;
            t2s[ty + i*8][tx] = w1 + w2 - w3;
        }
        __syncthreads();
        #pragma unroll
        for (int i = 0; i < 4; i++) {
            size_t o = (size_t)(n0 + ty + i*8)*DD + k0 + tx;
            job.d1[o] = __float2half(t1s[tx][ty + i*8]);
            job.d2[o] = __float2half(t2s[tx][ty + i*8]);
        }
    }
}

// ========== GEMM 1: fused agg + K=512 GEMM + bias + relu ==========
// z=0: out = relu((g_gt prefix-agg A)@W^T + b); z=1: suffix (g_lt)
struct GemmPairA {
    const __half *A[2], *W[2];
    const float *bias[2];
    __half *outH[2];
};

__device__ __forceinline__ void load_chunk(uint32_t smbase, const __half* Asrc,
                                           const __half* Wsrc, int bm, int bn,
                                           int kk, int tid) {
    #pragma unroll
    for (int j = 0; j < 4; j++) {
        int f = tid + 256*j; int row = f >> 3, c = f & 7;
        cp_async16(smbase + row*(HPITCH*2) + c*16,
                   Asrc + (size_t)(bm + row)*512 + kk + c*8);
    }
    #pragma unroll
    for (int j = 0; j < 4; j++) {
        int f = tid + 256*j; int row = f >> 3, c = f & 7;
        cp_async16(smbase + ABYTES + row*(HPITCH*2) + c*16,
                   Wsrc + (size_t)(bn + row)*512 + kk + c*8);
    }
}

__global__ void __launch_bounds__(256, 2)
gemm_agg(GemmPairA P, const int* __restrict__ perm, const int* __restrict__ Vv)
{
    const int z = blockIdx.z;
    const __half* A = P.A[z]; const __half* W = P.W[z];
    const float* bias = P.bias[z];
    __half* outH = P.outH[z];

    extern __shared__ char sm[];
    const int bm = blockIdx.y * 128, bn = blockIdx.x * 128;
    const int tid = threadIdx.x, wid = tid >> 5, lane = tid & 31;
    const int wm = (wid >> 1) * 32, wn = (wid & 1) * 64;

    __shared__ int pm_s[128];
    __shared__ int V_s[4];
    if (tid < 128) pm_s[tid] = perm[bm + tid];
    if (tid < 4)   V_s[tid]  = Vv[(bm >> 5) + tid];

    // ldmatrix lane addressing (bytes)
    const int laneAr = (lane & 7) + ((lane & 8) ? 8 : 0);
    const int laneAc = (lane & 16) ? 8 : 0;
    const int laneBr = (lane & 7) + ((lane & 16) ? 8 : 0);
    const int laneBc = (lane & 8) ? 8 : 0;
    const uint32_t smb = smem_u32(sm);
    uint32_t aAddr[2], bAddr[4];
    #pragma unroll
    for (int mi = 0; mi < 2; mi++)
        aAddr[mi] = smb + ((wm + mi*16 + laneAr)*HPITCH + laneAc)*2;
    #pragma unroll
    for (int p = 0; p < 4; p++)
        bAddr[p] = smb + ABYTES + ((wn + p*16 + laneBr)*HPITCH + laneBc)*2;

    float acc[2][8][4];
    #pragma unroll
    for (int i = 0; i < 2; i++)
        #pragma unroll
        for (int j = 0; j < 8; j++)
            #pragma unroll
            for (int q = 0; q < 4; q++) acc[i][j][q] = 0.f;

    const int NC = 512 / KCH;   // 8
    load_chunk(smb, A, W, bm, bn, 0, tid);
    asm volatile("cp.async.commit_group;");
    load_chunk(smb + STGB, A, W, bm, bn, KCH, tid);
    asm volatile("cp.async.commit_group;");

    int rs = 0, ws = 2;
    #pragma unroll 1
    for (int kc = 0; kc < NC; kc++) {
        if (kc + 1 < NC) asm volatile("cp.async.wait_group 1;");
        else             asm volatile("cp.async.wait_group 0;");
        __syncthreads();

        if (kc + 2 < NC) {
            load_chunk(smb + ws*STGB, A, W, bm, bn, (kc + 2)*KCH, tid);
            asm volatile("cp.async.commit_group;");
        }

        // ---- fused aggregation: in-place scan of the A tile (warp = batch) ----
        if (wid < 4) {
            const int* pmb = pm_s + wid*32;
            const int V = V_s[wid];
            char* batchBase = sm + rs*STGB + (wid*32)*(HPITCH*2);
            float2 run = make_float2(0.f, 0.f);
            if (z == 0) {       // g_gt: prefix over ranks
                #pragma unroll
                for (int rr = 0; rr < NN; rr++) {
                    if (rr < V) {
                        __half2* pp = (__half2*)(batchBase + pmb[rr]*(HPITCH*2)) + lane;
                        float2 x = __half22float2(*pp);
                        run.x += x.x; run.y += x.y;
                        const float inv = 1.f/(float)(rr + 1);
                        *pp = __floats2half2_rn(run.x*inv, run.y*inv);
                    }
                }
            } else {            // g_lt: suffix over ranks
                #pragma unroll
                for (int rr = 0; rr < NN; rr++) {
                    if (rr < V) {
                        __half2* pp = (__half2*)(batchBase + pmb[V-1-rr]*(HPITCH*2)) + lane;
                        float2 x = __half22float2(*pp);
                        run.x += x.x; run.y += x.y;
                        const float inv = 1.f/(float)(rr + 1);
                        *pp = __floats2half2_rn(run.x*inv, run.y*inv);
                    }
                }
            }
        }
        __syncthreads();

        const uint32_t soff = (uint32_t)rs * STGB;
        #pragma unroll
        for (int s4 = 0; s4 < 4; s4++) {
            const uint32_t koff = soff + s4*32;
            uint32_t aF[2][4], bF[4][4];
            ldsm_x4(aAddr[0] + koff, aF[0]);
            ldsm_x4(aAddr[1] + koff, aF[1]);
            #pragma unroll
            for (int p = 0; p < 4; p++) ldsm_x4(bAddr[p] + koff, bF[p]);
            #pragma unroll
            for (int p = 0; p < 4; p++) {
                mma_f16(acc[0][2*p],   aF[0], bF[p][0], bF[p][1]);
                mma_f16(acc[1][2*p],   aF[1], bF[p][0], bF[p][1]);
                mma_f16(acc[0][2*p+1], aF[0], bF[p][2], bF[p][3]);
                mma_f16(acc[1][2*p+1], aF[1], bF[p][2], bF[p][3]);
            }
        }
        rs = (rs + 1 == NSTG) ? 0 : rs + 1;
        ws = (ws + 1 == NSTG) ? 0 : ws + 1;
    }

    // epilogue: bias + relu -> fp16
    const int r0 = bm + wm + (lane >> 2);
    const int cbase = bn + wn + (lane & 3)*2;
    float bb0[8], bb1[8];
    #pragma unroll
    for (int ni = 0; ni < 8; ni++) {
        bb0[ni] = bias[cbase + ni*8];
        bb1[ni] = bias[cbase + ni*8 + 1];
    }
    #pragma unroll
    for (int mi = 0; mi < 2; mi++) {
        int row0 = r0 + mi*16, row1 = row0 + 8;
        #pragma unroll
        for (int ni = 0; ni < 8; ni++) {
            int col = cbase + ni*8;
            float v0 = fmaxf(acc[mi][ni][0] + bb0[ni], 0.f);
            float v1 = fmaxf(acc[mi][ni][1] + bb1[ni], 0.f);
            float v2 = fmaxf(acc[mi][ni][2] + bb0[ni], 0.f);
            float v3 = fmaxf(acc[mi][ni][3] + bb1[ni], 0.f);
            *(__half2*)(outH + (size_t)row0*512 + col) = __floats2half2_rn(v0, v1);
            *(__half2*)(outH + (size_t)row1*512 + col) = __floats2half2_rn(v2, v3);
        }
    }
}

// ========== GEMM 2: K=1024 (A1|A2), 64x128 tile, fused gate / relu+residual ==========
// EPI 2: ninfo = sig(v+b)*e1 + (1-sig)*e2  -> outH
// EPI 3: node = relu(v+b) -> outH(fp16) + outF(fp32); optional out2 = addsrc + node
struct Gemm1024 {
    const __half *A1, *A2, *W1, *W2;
    const float *bias;
    const __half *e1, *e2;
    __half *outH; float *outF;
    const float *addsrc; float *out2;
};

__device__ __forceinline__ void load_chunk1024(uint32_t smbase, const Gemm1024& P,
                                               int bm, int bn, int kk, int tid) {
    const __half* Asrc = (kk < 512) ? P.A1 : P.A2;
    const __half* Wsrc = (kk < 512) ? P.W1 : P.W2;
    const int k2 = kk & 511;
    #pragma unroll
    for (int j = 0; j < 2; j++) {
        int f = tid + 256*j; int row = f >> 3, c = f & 7;
        cp_async16(smbase + row*(HPITCH*2) + c*16,
                   Asrc + (size_t)(bm + row)*512 + k2 + c*8);
    }
    #pragma unroll
    for (int j = 0; j < 4; j++) {
        int f = tid + 256*j; int row = f >> 3, c = f & 7;
        cp_async16(smbase + ABYTES2 + row*(HPITCH*2) + c*16,
                   Wsrc + (size_t)(bn + row)*512 + k2 + c*8);
    }
}

template<int EPI>
__global__ void __launch_bounds__(256, 2)
gemm_k1024(Gemm1024 P)
{
    extern __shared__ char sm[];
    const int bm = blockIdx.y * 64, bn = blockIdx.x * 128;
    const int tid = threadIdx.x, wid = tid >> 5, lane = tid & 31;
    const int wm = (wid >> 2) * 32, wn = (wid & 3) * 32;

    const int laneAr = (lane & 7) + ((lane & 8) ? 8 : 0);
    const int laneAc = (lane & 16) ? 8 : 0;
    const int laneBr = (lane & 7) + ((lane & 16) ? 8 : 0);
    const int laneBc = (lane & 8) ? 8 : 0;
    const uint32_t smb = smem_u32(sm);
    uint32_t aAddr[2], bAddr[2];
    #pragma unroll
    for (int mi = 0; mi < 2; mi++)
        aAddr[mi] = smb + ((wm + mi*16 + laneAr)*HPITCH + laneAc)*2;
    #pragma unroll
    for (int p = 0; p < 2; p++)
        bAddr[p] = smb + ABYTES2 + ((wn + p*16 + laneBr)*HPITCH + laneBc)*2;

    float acc[2][4][4];
    #pragma unroll
    for (int i = 0; i < 2; i++)
        #pragma unroll
        for (int j = 0; j < 4; j++)
            #pragma unroll
            for (int q = 0; q < 4; q++) acc[i][j][q] = 0.f;

    const int NC = 1024 / KCH;   // 16
    load_chunk1024(smb, P, bm, bn, 0, tid);
    asm volatile("cp.async.commit_group;");
    load_chunk1024(smb + STGB2, P, bm, bn, KCH, tid);
    asm volatile("cp.async.commit_group;");

    int rs = 0, ws = 2;
    #pragma unroll 1
    for (int kc = 0; kc < NC; kc++) {
        if (kc + 1 < NC) asm volatile("cp.async.wait_group 1;");
        else             asm volatile("cp.async.wait_group 0;");
        __syncthreads();

        if (kc + 2 < NC) {
            load_chunk1024(smb + ws*STGB2, P, bm, bn, (kc + 2)*KCH, tid);
            asm volatile("cp.async.commit_group;");
        }

        const uint32_t soff = (uint32_t)rs * STGB2;
        #pragma unroll
        for (int s4 = 0; s4 < 4; s4++) {
            const uint32_t koff = soff + s4*32;
            uint32_t aF[2][4], bF[2][4];
            ldsm_x4(aAddr[0] + koff, aF[0]);
            ldsm_x4(aAddr[1] + koff, aF[1]);
            #pragma unroll
            for (int p = 0; p < 2; p++) ldsm_x4(bAddr[p] + koff, bF[p]);
            #pragma unroll
            for (int p = 0; p < 2; p++) {
                mma_f16(acc[0][2*p],   aF[0], bF[p][0], bF[p][1]);
                mma_f16(acc[1][2*p],   aF[1], bF[p][0], bF[p][1]);
                mma_f16(acc[0][2*p+1], aF[0], bF[p][2], bF[p][3]);
                mma_f16(acc[1][2*p+1], aF[1], bF[p][2], bF[p][3]);
            }
        }
        rs = (rs + 1 == NSTG) ? 0 : rs + 1;
        ws = (ws + 1 == NSTG) ? 0 : ws + 1;
    }

    // epilogue
    const int r0 = bm + wm + (lane >> 2);
    const int cbase = bn + wn + (lane & 3)*2;
    float bb0[4], bb1[4];
    #pragma unroll
    for (int ni = 0; ni < 4; ni++) {
        bb0[ni] = P.bias[cbase + ni*8];
        bb1[ni] = P.bias[cbase + ni*8 + 1];
    }
    #pragma unroll
    for (int mi = 0; mi < 2; mi++) {
        int row0 = r0 + mi*16, row1 = row0 + 8;
        #pragma unroll
        for (int ni = 0; ni < 4; ni++) {
            int col = cbase + ni*8;
            float v0 = acc[mi][ni][0] + bb0[ni];
            float v1 = acc[mi][ni][1] + bb1[ni];
            float v2 = acc[mi][ni][2] + bb0[ni];
            float v3 = acc[mi][ni][3] + bb1[ni];
            if (EPI == 2) {
                float2 x0 = __half22float2(*(const __half2*)(P.e1 + (size_t)row0*512 + col));
                float2 y0 = __half22float2(*(const __half2*)(P.e2 + (size_t)row0*512 + col));
                float2 x1 = __half22float2(*(const __half2*)(P.e1 + (size_t)row1*512 + col));
                float2 y1 = __half22float2(*(const __half2*)(P.e2 + (size_t)row1*512 + col));
                float g0 = 1.f/(1.f + expf(-v0));
                float g1 = 1.f/(1.f + expf(-v1));
                float g2 = 1.f/(1.f + expf(-v2));
                float g3 = 1.f/(1.f + expf(-v3));
                v0 = g0*x0.x + (1.f-g0)*y0.x;
                v1 = g1*x0.y + (1.f-g1)*y0.y;
                v2 = g2*x1.x + (1.f-g2)*y1.x;
                v3 = g3*x1.y + (1.f-g3)*y1.y;
                *(__half2*)(P.outH + (size_t)row0*512 + col) = __floats2half2_rn(v0, v1);
                *(__half2*)(P.outH + (size_t)row1*512 + col) = __floats2half2_rn(v2, v3);
            } else {
                v0 = fmaxf(v0, 0.f); v1 = fmaxf(v1, 0.f);
                v2 = fmaxf(v2, 0.f); v3 = fmaxf(v3, 0.f);
                *(__half2*)(P.outH + (size_t)row0*512 + col) = __floats2half2_rn(v0, v1);
                *(__half2*)(P.outH + (size_t)row1*512 + col) = __floats2half2_rn(v2, v3);
                *(float2*)(P.outF + (size_t)row0*512 + col) = make_float2(v0, v1);
                *(float2*)(P.outF + (size_t)row1*512 + col) = make_float2(v2, v3);
                if (P.addsrc) {
                    float2 s0 = *(const float2*)(P.addsrc + (size_t)row0*512 + col);
                    float2 s1 = *(const float2*)(P.addsrc + (size_t)row1*512 + col);
                    *(float2*)(P.out2 + (size_t)row0*512 + col) = make_float2(s0.x + v0, s0.y + v1);
                    *(float2*)(P.out2 + (size_t)row1*512 + col) = make_float2(s1.x + v2, s1.y + v3);
                }
            }
        }
    }
}

// ---------------- output assembly (float4, s split 8-ways + partial max) -------
__global__ void fused_assemble(const float4* __restrict__ enc,
                               const float4* __restrict__ node,
                               const int* __restrict__ invmap,
                               float4* __restrict__ gnn, float4* __restrict__ po_part) {
    int b = blockIdx.x, q = blockIdx.y, t = threadIdx.x;   // 128 threads, q in 0..7
    __shared__ int inv[64];
    if (t < 64) inv[t] = invmap[b*SS + q*64 + t];
    __syncthreads();
    float4 m = make_float4(-3.402823466e38f, -3.402823466e38f,
                           -3.402823466e38f, -3.402823466e38f);
    #pragma unroll 4
    for (int si = 0; si < 64; si++) {
        int s = q*64 + si;
        size_t o = ((size_t)s*BB + b)*128 + t;
        float4 v = enc[o];
        int iv = inv[si];
        if (iv >= 0) {
            float4 nv = node[(size_t)iv*128 + t];
            v.x += nv.x; v.y += nv.y; v.z += nv.z; v.w += nv.w;
        }
        gnn[o] = v;
        m.x = fmaxf(m.x, v.x); m.y = fmaxf(m.y, v.y);
        m.z = fmaxf(m.z, v.z); m.w = fmaxf(m.w, v.w);
    }
    po_part[((size_t)q*BB + b)*128 + t] = m;
}

__global__ void reduce_po(const float4* __restrict__ pp, float4* __restrict__ po) {
    int i = blockIdx.x*256 + threadIdx.x;      // BB*DD/4 = 16384
    float4 m = pp[i];
    #pragma unroll
    for (int q = 1; q < 8; q++) {
        float4 v = pp[i + q*16384];
        m.x = fmaxf(m.x, v.x); m.y = fmaxf(m.y, v.y);
        m.z = fmaxf(m.z, v.z); m.w = fmaxf(m.w, v.w);
    }
    po[i] = m;
}

// ---------------- host launch ----------------
extern "C" void kernel_launch(void* const* d_in, const int* in_sizes, int n_in,
                              void* d_out, int out_size) {
    const float* enc    = (const float*)d_in[0];   // [S,B,D]
    const float* numenc = (const float*)d_in[1];   // [B,N,D]
    const int*   pos    = (const int*)d_in[2];     // [B,N]
    const int*   order  = (const int*)d_in[3];     // [B,N]
    const float* w_n1a  = (const float*)d_in[4];
    const float* b_n1a  = (const float*)d_in[5];
    const float* w_n1b  = (const float*)d_in[6];
    const float* b_n1b  = (const float*)d_in[7];
    const float* w_n2a  = (const float*)d_in[8];
    const float* b_n2a  = (const float*)d_in[9];
    const float* w_n2b  = (const float*)d_in[10];
    const float* b_n2b  = (const float*)d_in[11];
    const float* w_g    = (const float*)d_in[12];  // [H,4D,D]
    const float* b_g    = (const float*)d_in[13];
    const float* w_o    = (const float*)d_in[14];  // [H,2D,D]
    const float* b_o    = (const float*)d_in[15];

    float* out     = (float*)d_out;
    float* out_gnn = out;                                    // [S,B,D]
    float* out_ne  = out + (size_t)SS*BB*DD;                 // [B,N,D]
    float* out_po  = out_ne + (size_t)BB*NN*DD;              // [B,D]

    float *nodeF, *popart;
    __half *numencH, *t3h, *t4h, *ni1h, *ni2h, *ninfoh, *nodeH0, *nodeH1, *WT;
    int *invmap, *perm, *Vv;
    cudaGetSymbolAddress((void**)&invmap,  invmap_buf);
    cudaGetSymbolAddress((void**)&perm,    perm_buf);
    cudaGetSymbolAddress((void**)&Vv,      V_buf);
    cudaGetSymbolAddress((void**)&nodeF,   buf_nodeF);
    cudaGetSymbolAddress((void**)&popart,  buf_popart);
    cudaGetSymbolAddress((void**)&numencH, buf_numencH);
    cudaGetSymbolAddress((void**)&t3h,     buf_t3h);
    cudaGetSymbolAddress((void**)&t4h,     buf_t4h);
    cudaGetSymbolAddress((void**)&ni1h,    buf_ni1h);
    cudaGetSymbolAddress((void**)&ni2h,    buf_ni2h);
    cudaGetSymbolAddress((void**)&ninfoh,  buf_ninfoh);
    cudaGetSymbolAddress((void**)&nodeH0,  buf_nodeH);
    nodeH1 = nodeH0 + (size_t)MM*DD;
    cudaGetSymbolAddress((void**)&WT,      buf_WT);

    cudaFuncSetAttribute(gemm_agg,      cudaFuncAttributeMaxDynamicSharedMemorySize, SMEM_DYN);
    cudaFuncSetAttribute(gemm_k1024<2>, cudaFuncAttributeMaxDynamicSharedMemorySize, SMEM_DYN2);
    cudaFuncSetAttribute(gemm_k1024<3>, cudaFuncAttributeMaxDynamicSharedMemorySize, SMEM_DYN2);

    build_meta<<<BB, SS>>>(order, pos, invmap, perm, Vv);
    f2h<<<512, 256>>>((const float2*)numenc, (__half2*)numencH, MM*DD/2);

    // all weight transposes in one launch (fp16 [N,K])
    {
        TArgs TA;
        for (int h = 0; h < HH; h++) {
            __half* base = WT + (size_t)h*8*DD*DD;
            TJob* j = TA.j + h*7;
            j[0] = { w_n1a + (size_t)h*DD*DD, base + 0*(size_t)DD*DD, nullptr, 0 };
            j[1] = { w_n1b + (size_t)h*DD*DD, base + 1*(size_t)DD*DD, nullptr, 0 };
            j[2] = { w_n2a + (size_t)h*DD*DD, base + 2*(size_t)DD*DD, nullptr, 0 };
            j[3] = { w_n2b + (size_t)h*DD*DD, base + 3*(size_t)DD*DD, nullptr, 0 };
            j[4] = { w_o + (size_t)h*2*DD*DD,                  base + 6*(size_t)DD*DD, nullptr, 0 };
            j[5] = { w_o + (size_t)h*2*DD*DD + (size_t)DD*DD,  base + 7*(size_t)DD*DD, nullptr, 0 };
            j[6] = { w_g + (size_t)h*4*DD*DD, base + 4*(size_t)DD*DD, base + 5*(size_t)DD*DD, 1 };
        }
        transpose_all<<<dim3(16,16,14), dim3(32,8)>>>(TA);
    }

    const dim3 ggrid(4, 32, 2);    // K=512 fused-agg GEMM pair
    const dim3 g1024(4, 64);       // K=1024 M-split GEMM
    const __half* node = numencH;
    __half* nodeOutH[2] = { nodeH0, nodeH1 };

    for (int h = 0; h < HH; h++) {
        __half* base = WT + (size_t)h*8*DD*DD;

        // v1 = relu((g_gt@node)@w1a + b), v2 = relu((g_lt@node)@w2a + b)
        {
            GemmPairA P = {};
            P.A[0]=node; P.W[0]=base+0*(size_t)DD*DD; P.bias[0]=b_n1a+h*DD; P.outH[0]=t3h;
            P.A[1]=node; P.W[1]=base+2*(size_t)DD*DD; P.bias[1]=b_n2a+h*DD; P.outH[1]=t4h;
            gemm_agg<<<ggrid, 256, SMEM_DYN>>>(P, perm, Vv);
        }

        // ni1 = relu((g_gt@v1)@w1b + b), ni2 = relu((g_lt@v2)@w2b + b)
        {
            GemmPairA P = {};
            P.A[0]=t3h; P.W[0]=base+1*(size_t)DD*DD; P.bias[0]=b_n1b+h*DD; P.outH[0]=ni1h;
            P.A[1]=t4h; P.W[1]=base+3*(size_t)DD*DD; P.bias[1]=b_n2b+h*DD; P.outH[1]=ni2h;
            gemm_agg<<<ggrid, 256, SMEM_DYN>>>(P, perm, Vv);
        }

        // ninfo = sig(ni1@Wg1 + ni2@Wg2 + b_g)*ni1 + (1-sig)*ni2
        {
            Gemm1024 P = {};
            P.A1=ni1h; P.A2=ni2h;
            P.W1=base+4*(size_t)DD*DD; P.W2=base+5*(size_t)DD*DD;
            P.bias=b_g+h*DD; P.e1=ni1h; P.e2=ni2h; P.outH=ninfoh;
            gemm_k1024<2><<<g1024, 256, SMEM_DYN2>>>(P);
        }

        // node' = relu(node@woA + ninfo@woB + b_o); last hop: out_ne = numenc + node'
        {
            Gemm1024 P = {};
            P.A1=node; P.A2=ninfoh;
            P.W1=base+6*(size_t)DD*DD; P.W2=base+7*(size_t)DD*DD;
            P.bias=b_o+h*DD; P.outH=nodeOutH[h]; P.outF=nodeF;
            if (h == HH-1) { P.addsrc = numenc; P.out2 = out_ne; }
            gemm_k1024<3><<<g1024, 256, SMEM_DYN2>>>(P);
        }
        node = nodeOutH[h];
    }

    // assemble: gnn = enc + scatter(node); po = colmax
    fused_assemble<<<dim3(BB,8), 128>>>((const float4*)enc, (const float4*)nodeF,
                                        invmap, (float4*)out_gnn, (float4*)popart);
    reduce_po<<<64, 256>>>((const float4*)popart, (float4*)out_po);
}

// round 11
// speedup vs baseline: 1.1177x; 1.1177x over previous
#include <cuda_runtime.h>
#include <cuda_fp16.h>
#include <math.h>
#include <stdint.h>

#define BB 128
#define SS 512
#define NN 32
#define DD 512
#define HH 2
#define MM (BB*NN)   // 4096 rows

#define KCH 64                  // fp16 elements per pipeline chunk (128 B/row)
#define HPITCH 72               // smem row pitch in halves (144 B, conflict-free ldsm)
#define ABYTES (128*HPITCH*2)   // 18432: 128-row operand per stage
#define STGB (2*ABYTES)         // 36864 per stage (A128 + B128)
#define NSTG 3
#define SMEM_DYN (NSTG*STGB)    // 110592 -> 2 CTAs/SM

#define ABYTES2 (64*HPITCH*2)   // 9216: 64-row A tile
#define STGB2 (ABYTES2 + ABYTES) // 27648 per stage (A64 + B128)
#define SMEM_DYN2 (NSTG*STGB2)  // 82944 -> 2 CTAs/SM

// ---------------- scratch (device globals; no allocation) ----------------
__device__ int   invmap_buf[BB*SS];
__device__ int   perm_buf[BB*NN];
__device__ int   V_buf[BB];
__device__ float  buf_nodeF[MM*DD];       // fp32 final node (for assembly)
__device__ float  buf_popart[8*BB*DD];    // assemble partial max
__device__ __half buf_numencH[MM*DD];
__device__ __half buf_t1h[MM*DD];
__device__ __half buf_t2h[MM*DD];
__device__ __half buf_t3h[MM*DD];
__device__ __half buf_t4h[MM*DD];
__device__ __half buf_ni1h[MM*DD];
__device__ __half buf_ni2h[MM*DD];
__device__ __half buf_ninfoh[MM*DD];
__device__ __half buf_nodeH[2][MM*DD];
__device__ __half buf_WT[16*DD*DD];       // transposed fp16 weights [N,K]

// ---------------- helpers ----------------
__device__ __forceinline__ uint32_t smem_u32(const void* p) {
    return (uint32_t)__cvta_generic_to_shared(p);
}
__device__ __forceinline__ void cp_async16(uint32_t dst, const void* src) {
    asm volatile("cp.async.cg.shared.global [%0], [%1], 16;" :: "r"(dst), "l"(src));
}
__device__ __forceinline__ void mma_f16(float* c, const uint32_t* a,
                                        uint32_t b0, uint32_t b1) {
    asm volatile("mma.sync.aligned.m16n8k16.row.col.f32.f16.f16.f32 "
                 "{%0,%1,%2,%3}, {%4,%5,%6,%7}, {%8,%9}, {%0,%1,%2,%3};"
                 : "+f"(c[0]), "+f"(c[1]), "+f"(c[2]), "+f"(c[3])
                 : "r"(a[0]), "r"(a[1]), "r"(a[2]), "r"(a[3]), "r"(b0), "r"(b1));
}
__device__ __forceinline__ void ldsm_x4(uint32_t addr, uint32_t* r) {
    asm volatile("ldmatrix.sync.aligned.m8n8.x4.shared.b16 {%0,%1,%2,%3}, [%4];"
                 : "=r"(r[0]), "=r"(r[1]), "=r"(r[2]), "=r"(r[3]) : "r"(addr));
}

// ---------------- meta: invmap + rank permutation + valid count ----------------
__global__ void build_meta(const int* __restrict__ order, const int* __restrict__ pos,
                           int* __restrict__ invmap, int* __restrict__ perm,
                           int* __restrict__ Vv) {
    int b = blockIdx.x, tid = threadIdx.x;    // 512 threads
    __shared__ int ord[NN];
    if (tid < NN) ord[tid] = order[b*NN + tid];
    invmap[b*SS + tid] = -1;
    __syncthreads();
    if (tid < NN) {
        int p = pos[b*NN + tid];
        if (p >= 0) invmap[b*SS + p] = b*NN + tid;
        int o = ord[tid];
        bool valid = o > 0;
        int cntLess = 0, cntValid = 0, cntPadB = 0;
        #pragma unroll
        for (int m = 0; m < NN; m++) {
            int om = ord[m];
            bool vm = om > 0;
            cntValid += vm ? 1 : 0;
            cntLess  += (vm && om < o) ? 1 : 0;
            cntPadB  += (!vm && m < tid) ? 1 : 0;
        }
        int r = valid ? cntLess : (cntValid + cntPadB);
        perm[b*NN + r] = tid;
        if (tid == 0) Vv[b] = cntValid;
    }
}

// ---------------- fp32 -> fp16 convert ----------------
__global__ void f2h(const float2* __restrict__ src, __half2* __restrict__ dst, int n2) {
    int i = blockIdx.x*blockDim.x + threadIdx.x;
    int stride = gridDim.x*blockDim.x;
    for (; i < n2; i += stride) dst[i] = __float22half2_rn(src[i]);
}

// ---------------- dual graph aggregation via prefix/suffix sums ----------------
// z=0: y1 = g_gt @ x0 (prefix).  z=1: y2 = g_lt @ x1 (suffix).
__global__ void __launch_bounds__(128)
graph_agg2(const __half2* __restrict__ x0, const __half2* __restrict__ x1,
           __half2* __restrict__ y1, __half2* __restrict__ y2,
           const int* __restrict__ perm, const int* __restrict__ Vv) {
    int b = blockIdx.x;
    int t = blockIdx.y*128 + threadIdx.x;      // half2 column 0..255
    __shared__ int pm[NN];
    __shared__ int Vs;
    if (threadIdx.x < NN) pm[threadIdx.x] = perm[b*NN + threadIdx.x];
    if (threadIdx.x == 0) Vs = Vv[b];
    __syncthreads();
    const int V = Vs;
    const size_t base = (size_t)b*NN*256 + t;

    float2 xv[NN];
    float2 run = make_float2(0.f, 0.f);
    if (blockIdx.z == 0) {
        #pragma unroll
        for (int rr = 0; rr < NN; rr++)
            xv[rr] = __half22float2(x0[base + (size_t)pm[rr]*256]);
        #pragma unroll
        for (int rr = 0; rr < NN; rr++) {
            const float inv = 1.f/(float)(rr + 1);
            float2 o;
            if (rr < V) {
                o.x = (run.x + xv[rr].x) * inv;
                o.y = (run.y + xv[rr].y) * inv;
                run.x += xv[rr].x; run.y += xv[rr].y;
            } else {
                o = xv[rr];
            }
            y1[base + (size_t)pm[rr]*256] = __floats2half2_rn(o.x, o.y);
        }
    } else {
        #pragma unroll
        for (int rr = 0; rr < NN; rr++) {
            int sr = (rr < V) ? (V - 1 - rr) : rr;
            xv[rr] = __half22float2(x1[base + (size_t)pm[sr]*256]);
        }
        #pragma unroll
        for (int rr = 0; rr < NN; rr++) {
            const float inv = 1.f/(float)(rr + 1);
            int sr = (rr < V) ? (V - 1 - rr) : rr;
            float2 o;
            if (rr < V) {
                o.x = (run.x + xv[rr].x) * inv;
                o.y = (run.y + xv[rr].y) * inv;
                run.x += xv[rr].x; run.y += xv[rr].y;
            } else {
                o = xv[rr];
            }
            y2[base + (size_t)pm[sr]*256] = __floats2half2_rn(o.x, o.y);
        }
    }
}

// ---------------- single-launch weight transpose ([K,N]->[N,K] fp16) -----------
struct TJob { const float* src; __half* d1; __half* d2; int gate; };
struct TArgs { TJob j[14]; };

__global__ void transpose_all(TArgs A) {
    TJob job = A.j[blockIdx.z];
    __shared__ float t1s[32][33], t2s[32][33];
    int k0 = blockIdx.x*32, n0 = blockIdx.y*32;
    int tx = threadIdx.x, ty = threadIdx.y;
    if (!job.gate) {
        #pragma unroll
        for (int i = 0; i < 4; i++)
            t1s[ty + i*8][tx] = job.src[(size_t)(k0 + ty + i*8)*DD + n0 + tx];
        __syncthreads();
        #pragma unroll
        for (int i = 0; i < 4; i++)
            job.d1[(size_t)(n0 + ty + i*8)*DD + k0 + tx] = __float2half(t1s[tx][ty + i*8]);
    } else {
        #pragma unroll
        for (int i = 0; i < 4; i++) {
            int k = k0 + ty + i*8, n = n0 + tx;
            float w0 = job.src[(size_t)k*DD + n];
            float w1 = job.src[(size_t)(DD + k)*DD + n];
            float w2 = job.src[(size_t)(2*DD + k)*DD + n];
            float w3 = job.src[(size_t)(3*DD + k)*DD + n];
            t1s[ty + i*8][tx] = w0 + w2 + w3;
            t2s[ty + i*8][tx] = w1 + w2 - w3;
        }
        __syncthreads();
        #pragma unroll
        for (int i = 0; i < 4; i++) {
            size_t o = (size_t)(n0 + ty + i*8)*DD + k0 + tx;
            job.d1[o] = __float2half(t1s[tx][ty + i*8]);
            job.d2[o] = __float2half(t2s[tx][ty + i*8]);
        }
    }
}

// ========== GEMM 1: K=512 pair, 128x128 tile, bias + relu ==========
struct GemmPairA {
    const __half *A[2], *W[2];
    const float *bias[2];
    __half *outH[2];
};

__device__ __forceinline__ void load_chunk(uint32_t smbase, const __half* Asrc,
                                           const __half* Wsrc, int bm, int bn,
                                           int kk, int tid) {
    #pragma unroll
    for (int j = 0; j < 4; j++) {
        int f = tid + 256*j; int row = f >> 3, c = f & 7;
        cp_async16(smbase + row*(HPITCH*2) + c*16,
                   Asrc + (size_t)(bm + row)*512 + kk + c*8);
    }
    #pragma unroll
    for (int j = 0; j < 4; j++) {
        int f = tid + 256*j; int row = f >> 3, c = f & 7;
        cp_async16(smbase + ABYTES + row*(HPITCH*2) + c*16,
                   Wsrc + (size_t)(bn + row)*512 + kk + c*8);
    }
}

__global__ void __launch_bounds__(256, 2)
gemm_pair(GemmPairA P)
{
    const int z = blockIdx.z;
    const __half* A = P.A[z]; const __half* W = P.W[z];
    const float* bias = P.bias[z];
    __half* outH = P.outH[z];

    extern __shared__ char sm[];
    const int bm = blockIdx.y * 128, bn = blockIdx.x * 128;
    const int tid = threadIdx.x, wid = tid >> 5, lane = tid & 31;
    const int wm = (wid >> 1) * 32, wn = (wid & 1) * 64;

    const int laneAr = (lane & 7) + ((lane & 8) ? 8 : 0);
    const int laneAc = (lane & 16) ? 8 : 0;
    const int laneBr = (lane & 7) + ((lane & 16) ? 8 : 0);
    const int laneBc = (lane & 8) ? 8 : 0;
    const uint32_t smb = smem_u32(sm);
    uint32_t aAddr[2], bAddr[4];
    #pragma unroll
    for (int mi = 0; mi < 2; mi++)
        aAddr[mi] = smb + ((wm + mi*16 + laneAr)*HPITCH + laneAc)*2;
    #pragma unroll
    for (int p = 0; p < 4; p++)
        bAddr[p] = smb + ABYTES + ((wn + p*16 + laneBr)*HPITCH + laneBc)*2;

    float acc[2][8][4];
    #pragma unroll
    for (int i = 0; i < 2; i++)
        #pragma unroll
        for (int j = 0; j < 8; j++)
            #pragma unroll
            for (int q = 0; q < 4; q++) acc[i][j][q] = 0.f;

    const int NC = 512 / KCH;   // 8
    load_chunk(smb, A, W, bm, bn, 0, tid);
    asm volatile("cp.async.commit_group;");
    load_chunk(smb + STGB, A, W, bm, bn, KCH, tid);
    asm volatile("cp.async.commit_group;");

    int rs = 0, ws = 2;
    #pragma unroll 1
    for (int kc = 0; kc < NC; kc++) {
        if (kc + 1 < NC) asm volatile("cp.async.wait_group 1;");
        else             asm volatile("cp.async.wait_group 0;");
        __syncthreads();

        if (kc + 2 < NC) {
            load_chunk(smb + ws*STGB, A, W, bm, bn, (kc + 2)*KCH, tid);
            asm volatile("cp.async.commit_group;");
        }

        const uint32_t soff = (uint32_t)rs * STGB;
        #pragma unroll
        for (int s4 = 0; s4 < 4; s4++) {
            const uint32_t koff = soff + s4*32;
            uint32_t aF[2][4], bF[4][4];
            ldsm_x4(aAddr[0] + koff, aF[0]);
            ldsm_x4(aAddr[1] + koff, aF[1]);
            #pragma unroll
            for (int p = 0; p < 4; p++) ldsm_x4(bAddr[p] + koff, bF[p]);
            #pragma unroll
            for (int p = 0; p < 4; p++) {
                mma_f16(acc[0][2*p],   aF[0], bF[p][0], bF[p][1]);
                mma_f16(acc[1][2*p],   aF[1], bF[p][0], bF[p][1]);
                mma_f16(acc[0][2*p+1], aF[0], bF[p][2], bF[p][3]);
                mma_f16(acc[1][2*p+1], aF[1], bF[p][2], bF[p][3]);
            }
        }
        rs = (rs + 1 == NSTG) ? 0 : rs + 1;
        ws = (ws + 1 == NSTG) ? 0 : ws + 1;
    }

    const int r0 = bm + wm + (lane >> 2);
    const int cbase = bn + wn + (lane & 3)*2;
    float bb0[8], bb1[8];
    #pragma unroll
    for (int ni = 0; ni < 8; ni++) {
        bb0[ni] = bias[cbase + ni*8];
        bb1[ni] = bias[cbase + ni*8 + 1];
    }
    #pragma unroll
    for (int mi = 0; mi < 2; mi++) {
        int row0 = r0 + mi*16, row1 = row0 + 8;
        #pragma unroll
        for (int ni = 0; ni < 8; ni++) {
            int col = cbase + ni*8;
            float v0 = fmaxf(acc[mi][ni][0] + bb0[ni], 0.f);
            float v1 = fmaxf(acc[mi][ni][1] + bb1[ni], 0.f);
            float v2 = fmaxf(acc[mi][ni][2] + bb0[ni], 0.f);
            float v3 = fmaxf(acc[mi][ni][3] + bb1[ni], 0.f);
            *(__half2*)(outH + (size_t)row0*512 + col) = __floats2half2_rn(v0, v1);
            *(__half2*)(outH + (size_t)row1*512 + col) = __floats2half2_rn(v2, v3);
        }
    }
}

// ========== GEMM 2: K=1024 (A1|A2), 64x128 tile, fused gate / relu+residual ==========
struct Gemm1024 {
    const __half *A1, *A2, *W1, *W2;
    const float *bias;
    const __half *e1, *e2;
    __half *outH; float *outF;
    const float *addsrc; float *out2;
};

__device__ __forceinline__ void load_chunk1024(uint32_t smbase, const Gemm1024& P,
                                               int bm, int bn, int kk, int tid) {
    const __half* Asrc = (kk < 512) ? P.A1 : P.A2;
    const __half* Wsrc = (kk < 512) ? P.W1 : P.W2;
    const int k2 = kk & 511;
    #pragma unroll
    for (int j = 0; j < 2; j++) {
        int f = tid + 256*j; int row = f >> 3, c = f & 7;
        cp_async16(smbase + row*(HPITCH*2) + c*16,
                   Asrc + (size_t)(bm + row)*512 + k2 + c*8);
    }
    #pragma unroll
    for (int j = 0; j < 4; j++) {
        int f = tid + 256*j; int row = f >> 3, c = f & 7;
        cp_async16(smbase + ABYTES2 + row*(HPITCH*2) + c*16,
                   Wsrc + (size_t)(bn + row)*512 + k2 + c*8);
    }
}

template<int EPI>
__global__ void __launch_bounds__(256, 2)
gemm_k1024(Gemm1024 P)
{
    extern __shared__ char sm[];
    const int bm = blockIdx.y * 64, bn = blockIdx.x * 128;
    const int tid = threadIdx.x, wid = tid >> 5, lane = tid & 31;
    const int wm = (wid >> 2) * 32, wn = (wid & 3) * 32;

    const int laneAr = (lane & 7) + ((lane & 8) ? 8 : 0);
    const int laneAc = (lane & 16) ? 8 : 0;
    const int laneBr = (lane & 7) + ((lane & 16) ? 8 : 0);
    const int laneBc = (lane & 8) ? 8 : 0;
    const uint32_t smb = smem_u32(sm);
    uint32_t aAddr[2], bAddr[2];
    #pragma unroll
    for (int mi = 0; mi < 2; mi++)
        aAddr[mi] = smb + ((wm + mi*16 + laneAr)*HPITCH + laneAc)*2;
    #pragma unroll
    for (int p = 0; p < 2; p++)
        bAddr[p] = smb + ABYTES2 + ((wn + p*16 + laneBr)*HPITCH + laneBc)*2;

    float acc[2][4][4];
    #pragma unroll
    for (int i = 0; i < 2; i++)
        #pragma unroll
        for (int j = 0; j < 4; j++)
            #pragma unroll
            for (int q = 0; q < 4; q++) acc[i][j][q] = 0.f;

    const int NC = 1024 / KCH;   // 16
    load_chunk1024(smb, P, bm, bn, 0, tid);
    asm volatile("cp.async.commit_group;");
    load_chunk1024(smb + STGB2, P, bm, bn, KCH, tid);
    asm volatile("cp.async.commit_group;");

    int rs = 0, ws = 2;
    #pragma unroll 1
    for (int kc = 0; kc < NC; kc++) {
        if (kc + 1 < NC) asm volatile("cp.async.wait_group 1;");
        else             asm volatile("cp.async.wait_group 0;");
        __syncthreads();

        if (kc + 2 < NC) {
            load_chunk1024(smb + ws*STGB2, P, bm, bn, (kc + 2)*KCH, tid);
            asm volatile("cp.async.commit_group;");
        }

        const uint32_t soff = (uint32_t)rs * STGB2;
        #pragma unroll
        for (int s4 = 0; s4 < 4; s4++) {
            const uint32_t koff = soff + s4*32;
            uint32_t aF[2][4], bF[2][4];
            ldsm_x4(aAddr[0] + koff, aF[0]);
            ldsm_x4(aAddr[1] + koff, aF[1]);
            #pragma unroll
            for (int p = 0; p < 2; p++) ldsm_x4(bAddr[p] + koff, bF[p]);
            #pragma unroll
            for (int p = 0; p < 2; p++) {
                mma_f16(acc[0][2*p],   aF[0], bF[p][0], bF[p][1]);
                mma_f16(acc[1][2*p],   aF[1], bF[p][0], bF[p][1]);
                mma_f16(acc[0][2*p+1], aF[0], bF[p][2], bF[p][3]);
                mma_f16(acc[1][2*p+1], aF[1], bF[p][2], bF[p][3]);
            }
        }
        rs = (rs + 1 == NSTG) ? 0 : rs + 1;
        ws = (ws + 1 == NSTG) ? 0 : ws + 1;
    }

    const int r0 = bm + wm + (lane >> 2);
    const int cbase = bn + wn + (lane & 3)*2;
    float bb0[4], bb1[4];
    #pragma unroll
    for (int ni = 0; ni < 4; ni++) {
        bb0[ni] = P.bias[cbase + ni*8];
        bb1[ni] = P.bias[cbase + ni*8 + 1];
    }
    #pragma unroll
    for (int mi = 0; mi < 2; mi++) {
        int row0 = r0 + mi*16, row1 = row0 + 8;
        #pragma unroll
        for (int ni = 0; ni < 4; ni++) {
            int col = cbase + ni*8;
            float v0 = acc[mi][ni][0] + bb0[ni];
            float v1 = acc[mi][ni][1] + bb1[ni];
            float v2 = acc[mi][ni][2] + bb0[ni];
            float v3 = acc[mi][ni][3] + bb1[ni];
            if (EPI == 2) {
                float2 x0 = __half22float2(*(const __half2*)(P.e1 + (size_t)row0*512 + col));
                float2 y0 = __half22float2(*(const __half2*)(P.e2 + (size_t)row0*512 + col));
                float2 x1 = __half22float2(*(const __half2*)(P.e1 + (size_t)row1*512 + col));
                float2 y1 = __half22float2(*(const __half2*)(P.e2 + (size_t)row1*512 + col));
                float g0 = 1.f/(1.f + expf(-v0));
                float g1 = 1.f/(1.f + expf(-v1));
                float g2 = 1.f/(1.f + expf(-v2));
                float g3 = 1.f/(1.f + expf(-v3));
                v0 = g0*x0.x + (1.f-g0)*y0.x;
                v1 = g1*x0.y + (1.f-g1)*y0.y;
                v2 = g2*x1.x + (1.f-g2)*y1.x;
                v3 = g3*x1.y + (1.f-g3)*y1.y;
                *(__half2*)(P.outH + (size_t)row0*512 + col) = __floats2half2_rn(v0, v1);
                *(__half2*)(P.outH + (size_t)row1*512 + col) = __floats2half2_rn(v2, v3);
            } else {
                v0 = fmaxf(v0, 0.f); v1 = fmaxf(v1, 0.f);
                v2 = fmaxf(v2, 0.f); v3 = fmaxf(v3, 0.f);
                *(__half2*)(P.outH + (size_t)row0*512 + col) = __floats2half2_rn(v0, v1);
                *(__half2*)(P.outH + (size_t)row1*512 + col) = __floats2half2_rn(v2, v3);
                *(float2*)(P.outF + (size_t)row0*512 + col) = make_float2(v0, v1);
                *(float2*)(P.outF + (size_t)row1*512 + col) = make_float2(v2, v3);
                if (P.addsrc) {
                    float2 s0 = *(const float2*)(P.addsrc + (size_t)row0*512 + col);
                    float2 s1 = *(const float2*)(P.addsrc + (size_t)row1*512 + col);
                    *(float2*)(P.out2 + (size_t)row0*512 + col) = make_float2(s0.x + v0, s0.y + v1);
                    *(float2*)(P.out2 + (size_t)row1*512 + col) = make_float2(s1.x + v2, s1.y + v3);
                }
            }
        }
    }
}

// ---------------- output assembly (float4, s split 8-ways + partial max) -------
__global__ void fused_assemble(const float4* __restrict__ enc,
                               const float4* __restrict__ node,
                               const int* __restrict__ invmap,
                               float4* __restrict__ gnn, float4* __restrict__ po_part) {
    int b = blockIdx.x, q = blockIdx.y, t = threadIdx.x;   // 128 threads, q in 0..7
    __shared__ int inv[64];
    if (t < 64) inv[t] = invmap[b*SS + q*64 + t];
    __syncthreads();
    float4 m = make_float4(-3.402823466e38f, -3.402823466e38f,
                           -3.402823466e38f, -3.402823466e38f);
    #pragma unroll 4
    for (int si = 0; si < 64; si++) {
        int s = q*64 + si;
        size_t o = ((size_t)s*BB + b)*128 + t;
        float4 v = enc[o];
        int iv = inv[si];
        if (iv >= 0) {
            float4 nv = node[(size_t)iv*128 + t];
            v.x += nv.x; v.y += nv.y; v.z += nv.z; v.w += nv.w;
        }
        gnn[o] = v;
        m.x = fmaxf(m.x, v.x); m.y = fmaxf(m.y, v.y);
        m.z = fmaxf(m.z, v.z); m.w = fmaxf(m.w, v.w);
    }
    po_part[((size_t)q*BB + b)*128 + t] = m;
}

__global__ void reduce_po(const float4* __restrict__ pp, float4* __restrict__ po) {
    int i = blockIdx.x*256 + threadIdx.x;      // BB*DD/4 = 16384
    float4 m = pp[i];
    #pragma unroll
    for (int q = 1; q < 8; q++) {
        float4 v = pp[i + q*16384];
        m.x = fmaxf(m.x, v.x); m.y = fmaxf(m.y, v.y);
        m.z = fmaxf(m.z, v.z); m.w = fmaxf(m.w, v.w);
    }
    po[i] = m;
}

// ---------------- host launch ----------------
extern "C" void kernel_launch(void* const* d_in, const int* in_sizes, int n_in,
                              void* d_out, int out_size) {
    const float* enc    = (const float*)d_in[0];   // [S,B,D]
    const float* numenc = (const float*)d_in[1];   // [B,N,D]
    const int*   pos    = (const int*)d_in[2];     // [B,N]
    const int*   order  = (const int*)d_in[3];     // [B,N]
    const float* w_n1a  = (const float*)d_in[4];
    const float* b_n1a  = (const float*)d_in[5];
    const float* w_n1b  = (const float*)d_in[6];
    const float* b_n1b  = (const float*)d_in[7];
    const float* w_n2a  = (const float*)d_in[8];
    const float* b_n2a  = (const float*)d_in[9];
    const float* w_n2b  = (const float*)d_in[10];
    const float* b_n2b  = (const float*)d_in[11];
    const float* w_g    = (const float*)d_in[12];  // [H,4D,D]
    const float* b_g    = (const float*)d_in[13];
    const float* w_o    = (const float*)d_in[14];  // [H,2D,D]
    const float* b_o    = (const float*)d_in[15];

    float* out     = (float*)d_out;
    float* out_gnn = out;                                    // [S,B,D]
    float* out_ne  = out + (size_t)SS*BB*DD;                 // [B,N,D]
    float* out_po  = out_ne + (size_t)BB*NN*DD;              // [B,D]

    float *nodeF, *popart;
    __half *numencH, *t1h, *t2h, *t3h, *t4h, *ni1h, *ni2h, *ninfoh, *nodeH0, *nodeH1, *WT;
    int *invmap, *perm, *Vv;
    cudaGetSymbolAddress((void**)&invmap,  invmap_buf);
    cudaGetSymbolAddress((void**)&perm,    perm_buf);
    cudaGetSymbolAddress((void**)&Vv,      V_buf);
    cudaGetSymbolAddress((void**)&nodeF,   buf_nodeF);
    cudaGetSymbolAddress((void**)&popart,  buf_popart);
    cudaGetSymbolAddress((void**)&numencH, buf_numencH);
    cudaGetSymbolAddress((void**)&t1h,     buf_t1h);
    cudaGetSymbolAddress((void**)&t2h,     buf_t2h);
    cudaGetSymbolAddress((void**)&t3h,     buf_t3h);
    cudaGetSymbolAddress((void**)&t4h,     buf_t4h);
    cudaGetSymbolAddress((void**)&ni1h,    buf_ni1h);
    cudaGetSymbolAddress((void**)&ni2h,    buf_ni2h);
    cudaGetSymbolAddress((void**)&ninfoh,  buf_ninfoh);
    cudaGetSymbolAddress((void**)&nodeH0,  buf_nodeH);
    nodeH1 = nodeH0 + (size_t)MM*DD;
    cudaGetSymbolAddress((void**)&WT,      buf_WT);

    cudaFuncSetAttribute(gemm_pair,     cudaFuncAttributeMaxDynamicSharedMemorySize, SMEM_DYN);
    cudaFuncSetAttribute(gemm_k1024<2>, cudaFuncAttributeMaxDynamicSharedMemorySize, SMEM_DYN2);
    cudaFuncSetAttribute(gemm_k1024<3>, cudaFuncAttributeMaxDynamicSharedMemorySize, SMEM_DYN2);

    build_meta<<<BB, SS>>>(order, pos, invmap, perm, Vv);
    f2h<<<512, 256>>>((const float2*)numenc, (__half2*)numencH, MM*DD/2);

    // all weight transposes in one launch (fp16 [N,K])
    {
        TArgs TA;
        for (int h = 0; h < HH; h++) {
            __half* base = WT + (size_t)h*8*DD*DD;
            TJob* j = TA.j + h*7;
            j[0] = { w_n1a + (size_t)h*DD*DD, base + 0*(size_t)DD*DD, nullptr, 0 };
            j[1] = { w_n1b + (size_t)h*DD*DD, base + 1*(size_t)DD*DD, nullptr, 0 };
            j[2] = { w_n2a + (size_t)h*DD*DD, base + 2*(size_t)DD*DD, nullptr, 0 };
            j[3] = { w_n2b + (size_t)h*DD*DD, base + 3*(size_t)DD*DD, nullptr, 0 };
            j[4] = { w_o + (size_t)h*2*DD*DD,                  base + 6*(size_t)DD*DD, nullptr, 0 };
            j[5] = { w_o + (size_t)h*2*DD*DD + (size_t)DD*DD,  base + 7*(size_t)DD*DD, nullptr, 0 };
            j[6] = { w_g + (size_t)h*4*DD*DD, base + 4*(size_t)DD*DD, base + 5*(size_t)DD*DD, 1 };
        }
        transpose_all<<<dim3(16,16,14), dim3(32,8)>>>(TA);
    }

    const dim3 ggrid(4, 32, 2);    // K=512 GEMM pair
    const dim3 g1024(4, 64);       // K=1024 M-split GEMM
    const dim3 agrid(BB, 2, 2);    // agg: batch, col-half, phase
    const __half* node = numencH;
    __half* nodeOutH[2] = { nodeH0, nodeH1 };

    for (int h = 0; h < HH; h++) {
        __half* base = WT + (size_t)h*8*DD*DD;

        // u1 = g_gt @ node, u2 = g_lt @ node
        graph_agg2<<<agrid, 128>>>((const __half2*)node, (const __half2*)node,
                                   (__half2*)t1h, (__half2*)t2h, perm, Vv);

        // v1 = relu(u1@w1a + b), v2 = relu(u2@w2a + b)
        {
            GemmPairA P = {};
            P.A[0]=t1h; P.W[0]=base+0*(size_t)DD*DD; P.bias[0]=b_n1a+h*DD; P.outH[0]=t3h;
            P.A[1]=t2h; P.W[1]=base+2*(size_t)DD*DD; P.bias[1]=b_n2a+h*DD; P.outH[1]=t4h;
            gemm_pair<<<ggrid, 256, SMEM_DYN>>>(P);
        }

        // u1b = g_gt @ v1, u2b = g_lt @ v2
        graph_agg2<<<agrid, 128>>>((const __half2*)t3h, (const __half2*)t4h,
                                   (__half2*)t1h, (__half2*)t2h, perm, Vv);

        // ni1 = relu(u1b@w1b + b), ni2 = relu(u2b@w2b + b)
        {
            GemmPairA P = {};
            P.A[0]=t1h; P.W[0]=base+1*(size_t)DD*DD; P.bias[0]=b_n1b+h*DD; P.outH[0]=ni1h;
            P.A[1]=t2h; P.W[1]=base+3*(size_t)DD*DD; P.bias[1]=b_n2b+h*DD; P.outH[1]=ni2h;
            gemm_pair<<<ggrid, 256, SMEM_DYN>>>(P);
        }

        // ninfo = sig(ni1@Wg1 + ni2@Wg2 + b_g)*ni1 + (1-sig)*ni2
        {
            Gemm1024 P = {};
            P.A1=ni1h; P.A2=ni2h;
            P.W1=base+4*(size_t)DD*DD; P.W2=base+5*(size_t)DD*DD;
            P.bias=b_g+h*DD; P.e1=ni1h; P.e2=ni2h; P.outH=ninfoh;
            gemm_k1024<2><<<g1024, 256, SMEM_DYN2>>>(P);
        }

        // node' = relu(node@woA + ninfo@woB + b_o); last hop: out_ne = numenc + node'
        {
            Gemm1024 P = {};
            P.A1=node; P.A2=ninfoh;
            P.W1=base+6*(size_t)DD*DD; P.W2=base+7*(size_t)DD*DD;
            P.bias=b_o+h*DD; P.outH=nodeOutH[h]; P.outF=nodeF;
            if (h == HH-1) { P.addsrc = numenc; P.out2 = out_ne; }
            gemm_k1024<3><<<g1024, 256, SMEM_DYN2>>>(P);
        }
        node = nodeOutH[h];
    }

    // assemble: gnn = enc + scatter(node); po = colmax
    fused_assemble<<<dim3(BB,8), 128>>>((const float4*)enc, (const float4*)nodeF,
                                        invmap, (float4*)out_gnn, (float4*)popart);
    reduce_po<<<64, 256>>>((const float4*)popart, (float4*)out_po);
}